// round 17
// baseline (speedup 1.0000x reference)
#include <cuda_runtime.h>
#include <cstdint>
#include <cstddef>

#define B_      64
#define LQ      1024
#define LK      1024
#define DH      64
#define QT      16
#define CHUNK   128
#define NCH     (LK / CHUNK)   // 8
#define NU      (2 * NCH)      // 16 pipeline units (hi/mid per chunk)
#define NTHR    512
#define KP32    36             // K smem pitch in u32: bank=(4r+u)%32 -> conflict-free
#define SCP     1028           // sc pitch: score STS conflict-free
#define CAPP    288            // (z,j) pair capacity per warp (wsc = 576 floats)
#define TEMP_INV 0.125f

// smem: slot0 hi[128*36 u32] | slot1 mid[128*36 u32] (=9216 floats; reused as 16x576 scratch) | sc[16*1028]
#define KS_FLOATS   (2 * CHUNK * KP32)     // 9216
#define SC_FLOATS   (QT * SCP)             // 16448
#define SMEM_FLOATS (KS_FLOATS + SC_FLOATS)
#define SMEM_BYTES  (SMEM_FLOATS * 4)
#define WSCR        576                    // per-warp scratch floats (16*576 = 9216)
#define KMID_BYTE_OFF (CHUNK * KP32 * 4)   // byte offset of slot1 from slot0

#define KELEMS  (B_ * LK * DH)             // 4,194,304
#define KU32S   (KELEMS / 2)               // f16x2 words per split array

__device__ int      g_mask_kind;           // 0 = uint8/bool, 1 = int32, 2 = float32
__device__ unsigned g_khi[KU32S];          // K fp16 hi  (f16x2-packed), built per launch
__device__ unsigned g_kmid[KU32S];         // K fp16 mid residual

// pack two fp32 -> f16x2 (lo = x, hi = y)
__device__ __forceinline__ unsigned pack_h2(float x, float y) {
    unsigned r;
    asm("cvt.rn.f16x2.f32 %0, %1, %2;" : "=r"(r) : "f"(y), "f"(x));
    return r;
}
// unpack f16x2 -> two fp32
__device__ __forceinline__ void unpack_h2(unsigned p, float& x, float& y) {
    asm("{ .reg .f16 l, h; mov.b32 {l, h}, %2; cvt.f32.f16 %0, l; cvt.f32.f16 %1, h; }"
        : "=f"(x), "=f"(y) : "r"(p));
}

// ---- prep: K fp16 hi/mid split (byte-neutral) + mask-dtype detection ----
__global__ void prep_kernel(const float* __restrict__ k, const unsigned char* __restrict__ m) {
    if (blockIdx.x == 0 && threadIdx.x < 32) {
        uint4 u = ((const uint4*)m)[threadIdx.x];   // 512 bytes sample
        unsigned fl = 0;
        #pragma unroll
        for (int bt = 0; bt < 4; ++bt) {
            unsigned uu = (&u.x)[bt];
            if (uu & 0x000000FFu) fl |= 1u;
            if (uu & 0x0000FF00u) fl |= 2u;
            if (uu & 0x00FF0000u) fl |= 4u;
            if (uu & 0xFF000000u) fl |= 8u;
        }
        fl = __reduce_or_sync(0xFFFFFFFFu, fl);
        if (threadIdx.x == 0) {
            int kind;
            if ((fl & 0xEu) == 0)                 kind = 1;  // int32
            else if ((fl & 1u) == 0 && (fl & 8u)) kind = 2;  // float32
            else                                  kind = 0;  // uint8 / bool
            g_mask_kind = kind;
        }
    }
    int i = blockIdx.x * 256 + threadIdx.x;        // float4 index
    float4 kv = ((const float4*)k)[i];
    unsigned hA = pack_h2(kv.x, kv.y);
    unsigned hB = pack_h2(kv.z, kv.w);
    float hx, hy, hz, hw;
    unpack_h2(hA, hx, hy);
    unpack_h2(hB, hz, hw);
    unsigned mA = pack_h2(kv.x - hx, kv.y - hy);
    unsigned mB = pack_h2(kv.z - hz, kv.w - hw);
    ((uint2*)g_khi)[i]  = make_uint2(hA, hB);
    ((uint2*)g_kmid)[i] = make_uint2(mA, mB);
}

__device__ __forceinline__ void mma_f16(float& d0, float& d1, float& d2, float& d3,
                                        unsigned a0, unsigned a1, unsigned a2, unsigned a3,
                                        unsigned b0, unsigned b1) {
    asm("mma.sync.aligned.m16n8k16.row.col.f32.f16.f16.f32 "
        "{%0,%1,%2,%3}, {%4,%5,%6,%7}, {%8,%9}, {%0,%1,%2,%3};"
        : "+f"(d0), "+f"(d1), "+f"(d2), "+f"(d3)
        : "r"(a0), "r"(a1), "r"(a2), "r"(a3), "r"(b0), "r"(b1));
}

__device__ __forceinline__ void ldsm_x4(unsigned& r0, unsigned& r1, unsigned& r2, unsigned& r3,
                                        unsigned saddr) {
    asm volatile("ldmatrix.sync.aligned.m8n8.x4.shared.b16 {%0,%1,%2,%3}, [%4];"
                 : "=r"(r0), "=r"(r1), "=r"(r2), "=r"(r3) : "r"(saddr));
}

__device__ __forceinline__ void cp_async16(unsigned dst, const void* src) {
    asm volatile("cp.async.cg.shared.global [%0], [%1], 16;" :: "r"(dst), "l"(src) : "memory");
}
__device__ __forceinline__ void cp_commit() {
    asm volatile("cp.async.commit_group;" ::: "memory");
}
__device__ __forceinline__ void cp_wait0() {
    asm volatile("cp.async.wait_group 0;" ::: "memory");
}
__device__ __forceinline__ void pair_bar(int id) {
    asm volatile("bar.sync %0, 64;" :: "r"(id) : "memory");
}

// load 4 mask flags for elements [basei, basei+4) of one score row
__device__ __forceinline__ void mask4(const unsigned char* mrow8, const unsigned* mrow32,
                                      int mkind, int basei,
                                      bool& m0, bool& m1, bool& m2, bool& m3) {
    if (mkind == 0) {
        unsigned mu = *(const unsigned*)(mrow8 + basei);
        m0 = (mu & 0x000000FFu) != 0; m1 = (mu & 0x0000FF00u) != 0;
        m2 = (mu & 0x00FF0000u) != 0; m3 = (mu & 0xFF000000u) != 0;
    } else {
        uint4 mu = *(const uint4*)(mrow32 + basei);
        m0 = mu.x != 0; m1 = mu.y != 0; m2 = mu.z != 0; m3 = mu.w != 0;
    }
}

// --------------------------------------------------------------------------
// One CTA = 16 q-rows of one batch, 512 threads / 16 warps.
// QK^T: fp16x2 3-term compensated MMA over per-warp-pair cp.async pipeline.
// Sparsemax: scan1 packs validity into a register bitmap; scan2 uses
// UNORDERED per-lane compaction (bitmap + shfl_up prefix scan -- no serial
// ballot chain). tau iterations run on the compact (z,j) list. Final support
// compaction writes the (p,j) gather list into the dead score row (no
// in-place hazards) and scatters attn. Gather: 8-way MLP batched V loads.
// --------------------------------------------------------------------------
extern "C" __global__ void __launch_bounds__(NTHR, 2)
sparse_attn_kernel(const float* __restrict__ q,
                   const float* __restrict__ v,
                   const void*  __restrict__ maskp,
                   float* __restrict__ out,
                   float* __restrict__ attn,
                   int write_attn)
{
    extern __shared__ float sm[];
    unsigned* khi_s = (unsigned*)sm;               // slot0; slot1 at +KMID_BYTE_OFF
    float*    sc    = sm + KS_FLOATS;              // [QT][SCP]

    const int tid  = threadIdx.x;
    const int w    = tid >> 5;
    const int lane = tid & 31;
    const int b    = blockIdx.y;
    const int q0   = blockIdx.x * QT;
    const int mkind = g_mask_kind;

    // ---- Q subtile (w>>3) as f16x2 B fragments (hi + mid), 16 regs ----
    unsigned bh0[4], bh1[4], bm0[4], bm1[4];
    {
        const float* qb = q + ((size_t)(b * LQ + q0 + 8 * (w >> 3) + (lane >> 2))) * DH + 2 * (lane & 3);
        #pragma unroll
        for (int ks = 0; ks < 4; ++ks) {
            float2 p0 = *(const float2*)(qb + ks * 16);
            float2 p1 = *(const float2*)(qb + ks * 16 + 8);
            float f0 = p0.x * TEMP_INV, f1 = p0.y * TEMP_INV;
            float f2 = p1.x * TEMP_INV, f3 = p1.y * TEMP_INV;
            bh0[ks] = pack_h2(f0, f1);
            bh1[ks] = pack_h2(f2, f3);
            float h0, h1, h2, h3;
            unpack_h2(bh0[ks], h0, h1);
            unpack_h2(bh1[ks], h2, h3);
            bm0[ks] = pack_h2(f0 - h0, f1 - h1);
            bm1[ks] = pack_h2(f2 - h2, f3 - h3);
        }
    }
    const int pair = w & 7;
    const int kr0  = 16 * pair;
    const int ti   = (w >> 3) * 32 + lane;         // 0..63 within pair

    const unsigned sm_shared = (unsigned)__cvta_generic_to_shared(khi_s);

    // ldmatrix per-lane address (shared space), ks advances by 32 bytes
    unsigned lm_base;
    {
        int g  = lane >> 3;                        // matrix index 0..3
        int rl = lane & 7;
        int row = kr0 + rl + 8 * (g & 1);          // m1/m3 -> rows +8
        lm_base = sm_shared + (unsigned)(row * KP32 * 4 + (g >> 1) * 16);   // m2/m3 -> k+8
    }

    // per-thread pair-slice copy addresses: 16 rows x 128B per unit, 2 cp16/thread
    unsigned cdst[2];
    int      csrc[2];
    #pragma unroll
    for (int i = 0; i < 2; ++i) {
        int flat = ti + 64 * i;
        int r = flat >> 3, c16 = flat & 7;
        cdst[i] = (unsigned)((kr0 + r) * KP32 * 4 + c16 * 16);
        csrc[i] = (kr0 + r) * 32 + c16 * 4;        // u32 offset within chunk base
    }

    // ---- QK^T per-pair pipeline over 16 units ----
    {
        {
            const unsigned* gsrc = g_khi + (size_t)(b * LK) * 32;
            cp_async16(sm_shared + cdst[0], gsrc + csrc[0]);
            cp_async16(sm_shared + cdst[1], gsrc + csrc[1]);
            cp_commit();
        }

        float d0 = 0.f, d1 = 0.f, d2 = 0.f, d3 = 0.f;
        for (int u = 0; u < NU; ++u) {
            cp_wait0();
            pair_bar(pair + 1);
            if (u + 1 < NU) {
                int cn = (u + 1) >> 1;
                const unsigned* gsrc = (((u + 1) & 1) ? g_kmid : g_khi)
                                       + (size_t)(b * LK + cn * CHUNK) * 32;
                unsigned dstb = sm_shared + ((u + 1) & 1) * KMID_BYTE_OFF;
                cp_async16(dstb + cdst[0], gsrc + csrc[0]);
                cp_async16(dstb + cdst[1], gsrc + csrc[1]);
                cp_commit();
            }
            if (!(u & 1)) {
                d0 = d1 = d2 = d3 = 0.f;
                #pragma unroll
                for (int ks = 0; ks < 4; ++ks) {
                    unsigned a0, a1, a2, a3;
                    ldsm_x4(a0, a1, a2, a3, lm_base + ks * 32);
                    mma_f16(d0, d1, d2, d3, a0, a1, a2, a3, bm0[ks], bm1[ks]);
                    mma_f16(d0, d1, d2, d3, a0, a1, a2, a3, bh0[ks], bh1[ks]);
                }
            } else {
                #pragma unroll
                for (int ks = 0; ks < 4; ++ks) {
                    unsigned a0, a1, a2, a3;
                    ldsm_x4(a0, a1, a2, a3, lm_base + KMID_BYTE_OFF + ks * 32);
                    mma_f16(d0, d1, d2, d3, a0, a1, a2, a3, bh0[ks], bh1[ks]);
                }
                int c  = u >> 1;
                int kg = c * CHUNK + kr0 + (lane >> 2);
                int qc = 8 * (w >> 3) + 2 * (lane & 3);
                sc[qc * SCP + kg]           = d0;
                sc[(qc + 1) * SCP + kg]     = d1;
                sc[qc * SCP + kg + 8]       = d2;
                sc[(qc + 1) * SCP + kg + 8] = d3;
            }
        }
    }
    __syncthreads();   // scores visible; K slots become per-warp scratch

    // ---- sparsemax (warp w owns row w); mask read ONCE into register bitmap ----
    const float* zr = sc + w * SCP;
    float* wsc = sm + w * WSCR;
    const size_t rowoff = (size_t)(b * LQ + q0 + w) * LK;
    const unsigned char* mrow8  = (const unsigned char*)maskp + rowoff;
    const unsigned*      mrow32 = (const unsigned*)maskp + rowoff;

    // scan1: S, C over unmasked entries; validity bitmap (bit 4*t4+e = unmasked)
    unsigned vmask = 0;
    float S = 0.0f; int Cl = 0;
    #pragma unroll
    for (int t4 = 0; t4 < 8; ++t4) {
        int basei = 4 * lane + 128 * t4;
        float4 zv = *(const float4*)(zr + basei);
        bool m0, m1, m2, m3;
        mask4(mrow8, mrow32, mkind, basei, m0, m1, m2, m3);
        if (!m0) { S += zv.x; Cl++; vmask |= 1u << (4 * t4 + 0); }
        if (!m1) { S += zv.y; Cl++; vmask |= 1u << (4 * t4 + 1); }
        if (!m2) { S += zv.z; Cl++; vmask |= 1u << (4 * t4 + 2); }
        if (!m3) { S += zv.w; Cl++; vmask |= 1u << (4 * t4 + 3); }
    }
    #pragma unroll
    for (int o = 16; o; o >>= 1) S += __shfl_xor_sync(0xFFFFFFFFu, S, o);
    int C = __reduce_add_sync(0xFFFFFFFFu, Cl);

    float tau = 1.0e30f;
    int   cnt = 0;
    bool  listok = true;

    if (C > 0) {
        tau = (S - 1.0f) / (float)C;

        // scan2 (UNORDERED compaction): pass A = survivor bitmap + partial sum
        unsigned smask = 0;
        float s2 = 0.0f;
        #pragma unroll
        for (int t4 = 0; t4 < 8; ++t4) {
            int basei = 4 * lane + 128 * t4;
            float4 zv = *(const float4*)(zr + basei);
            #pragma unroll
            for (int e = 0; e < 4; ++e) {
                float z = (&zv.x)[e];
                if (((vmask >> (4 * t4 + e)) & 1u) && z > tau) {
                    s2 += z;
                    smask |= 1u << (4 * t4 + e);
                }
            }
        }
        int myc = __popc(smask);
        int incl = myc;
        #pragma unroll
        for (int o = 1; o < 32; o <<= 1) {
            int n = __shfl_up_sync(0xFFFFFFFFu, incl, o);
            if (lane >= o) incl += n;
        }
        int base = incl - myc;
        cnt = __shfl_sync(0xFFFFFFFFu, incl, 31);
        int c2 = cnt;
        #pragma unroll
        for (int o = 16; o; o >>= 1) s2 += __shfl_xor_sync(0xFFFFFFFFu, s2, o);

        // pass B: each lane writes its own contiguous range
        {
            unsigned mm = smask;
            int ps = base;
            while (mm) {
                int bidx = __ffs(mm) - 1;
                mm &= mm - 1;
                int j = 4 * lane + 128 * (bidx >> 2) + (bidx & 3);
                if (ps < CAPP) {
                    wsc[2 * ps]     = zr[j];
                    wsc[2 * ps + 1] = __int_as_float(j);
                }
                ps++;
            }
        }
        __syncwarp();

        if (cnt <= CAPP) {
            if (c2 != C) {
                S = s2; C = c2;
                tau = (S - 1.0f) / (float)C;
                for (int iter = 0; iter < 64; ++iter) {
                    float s3 = 0.0f; int c3l = 0;
                    for (int i = lane; i < cnt; i += 32) {
                        float2 e2 = *(const float2*)(wsc + 2 * i);
                        if (e2.x > tau) { s3 += e2.x; c3l++; }
                    }
                    int c3 = __reduce_add_sync(0xFFFFFFFFu, c3l);
                    #pragma unroll
                    for (int o = 16; o; o >>= 1) s3 += __shfl_xor_sync(0xFFFFFFFFu, s3, o);
                    if (c3 == C) break;
                    S = s3; C = c3;
                    tau = (S - 1.0f) / (float)C;
                }
            }
        } else {
            listok = false;
            if (c2 != C) {
                S = s2; C = c2;
                tau = (S - 1.0f) / (float)C;
                for (int iter = 0; iter < 64; ++iter) {
                    float s3 = 0.0f; int c3l = 0;
                    #pragma unroll
                    for (int t4 = 0; t4 < 8; ++t4) {
                        int basei = 4 * lane + 128 * t4;
                        float4 zv = *(const float4*)(zr + basei);
                        #pragma unroll
                        for (int e = 0; e < 4; ++e) {
                            float z = (&zv.x)[e];
                            if (((vmask >> (4 * t4 + e)) & 1u) && z > tau) { s3 += z; c3l++; }
                        }
                    }
                    int c3 = __reduce_add_sync(0xFFFFFFFFu, c3l);
                    #pragma unroll
                    for (int o = 16; o; o >>= 1) s3 += __shfl_xor_sync(0xFFFFFFFFu, s3, o);
                    if (c3 == C) break;
                    S = s3; C = c3;
                    tau = (S - 1.0f) / (float)C;
                }
            }
        }
    }
    __syncwarp();

    // ---- epilogue: attn row + sparse attn@V ----
    const float2* vb2 = (const float2*)(v + (size_t)b * LK * DH);
    float* arow = attn + rowoff;
    float2 acc2 = make_float2(0.0f, 0.0f);
    const unsigned lt = (1u << lane) - 1u;

    if (listok) {
        if (write_attn) {
            const float4 z4 = make_float4(0.f, 0.f, 0.f, 0.f);
            #pragma unroll
            for (int t = 0; t < 8; ++t)
                *(float4*)(arow + 4 * lane + 128 * t) = z4;
        }
        __syncwarp();   // zero-fill done before scatter

        // final support compaction (UNORDERED, into dead score row) + attn scatter
        float* gl = sc + w * SCP;          // warp-private gather list (scores dead)
        // pass A: count survivors per lane
        int myc2 = 0;
        for (int i = lane; i < cnt; i += 32) {
            if (wsc[2 * i] > tau) myc2++;
        }
        int incl2 = myc2;
        #pragma unroll
        for (int o = 1; o < 32; o <<= 1) {
            int n = __shfl_up_sync(0xFFFFFFFFu, incl2, o);
            if (lane >= o) incl2 += n;
        }
        int base2 = incl2 - myc2;
        int ns = __shfl_sync(0xFFFFFFFFu, incl2, 31);
        // pass B: write (p, j) + scatter attn
        {
            int ps = base2;
            for (int i = lane; i < cnt; i += 32) {
                float2 e2 = *(const float2*)(wsc + 2 * i);
                float p = e2.x - tau;
                if (p > 0.0f) {
                    gl[2 * ps]     = p;
                    gl[2 * ps + 1] = e2.y;
                    if (write_attn) arow[__float_as_int(e2.y)] = p;
                    ps++;
                }
            }
        }
        __syncwarp();

        // batched V gather: 8 independent loads in flight
        int i = 0;
        for (; i + 8 <= ns; i += 8) {
            float4 e0 = *(const float4*)(gl + 2 * i);
            float4 e1 = *(const float4*)(gl + 2 * i + 4);
            float4 e2 = *(const float4*)(gl + 2 * i + 8);
            float4 e3 = *(const float4*)(gl + 2 * i + 12);
            const float2 v0 = vb2[__float_as_int(e0.y) * 32 + lane];
            const float2 v1 = vb2[__float_as_int(e0.w) * 32 + lane];
            const float2 v2 = vb2[__float_as_int(e1.y) * 32 + lane];
            const float2 v3 = vb2[__float_as_int(e1.w) * 32 + lane];
            const float2 v4 = vb2[__float_as_int(e2.y) * 32 + lane];
            const float2 v5 = vb2[__float_as_int(e2.w) * 32 + lane];
            const float2 v6 = vb2[__float_as_int(e3.y) * 32 + lane];
            const float2 v7 = vb2[__float_as_int(e3.w) * 32 + lane];
            acc2.x += e0.x * v0.x;  acc2.y += e0.x * v0.y;
            acc2.x += e0.z * v1.x;  acc2.y += e0.z * v1.y;
            acc2.x += e1.x * v2.x;  acc2.y += e1.x * v2.y;
            acc2.x += e1.z * v3.x;  acc2.y += e1.z * v3.y;
            acc2.x += e2.x * v4.x;  acc2.y += e2.x * v4.y;
            acc2.x += e2.z * v5.x;  acc2.y += e2.z * v5.y;
            acc2.x += e3.x * v6.x;  acc2.y += e3.x * v6.y;
            acc2.x += e3.z * v7.x;  acc2.y += e3.z * v7.y;
        }
        for (; i + 4 <= ns; i += 4) {
            float4 e0 = *(const float4*)(gl + 2 * i);
            float4 e1 = *(const float4*)(gl + 2 * i + 4);
            const float2 v0 = vb2[__float_as_int(e0.y) * 32 + lane];
            const float2 v1 = vb2[__float_as_int(e0.w) * 32 + lane];
            const float2 v2 = vb2[__float_as_int(e1.y) * 32 + lane];
            const float2 v3 = vb2[__float_as_int(e1.w) * 32 + lane];
            acc2.x += e0.x * v0.x;  acc2.y += e0.x * v0.y;
            acc2.x += e0.z * v1.x;  acc2.y += e0.z * v1.y;
            acc2.x += e1.x * v2.x;  acc2.y += e1.x * v2.y;
            acc2.x += e1.z * v3.x;  acc2.y += e1.z * v3.y;
        }
        for (; i < ns; ++i) {
            float p = gl[2 * i];
            int  j  = __float_as_int(gl[2 * i + 1]);
            const float2 vv = vb2[j * 32 + lane];
            acc2.x += p * vv.x;
            acc2.y += p * vv.y;
        }
    } else {
        // fallback (rare, support@tau0 > CAPP): ballot-compaction p-pass, bitmap inline
        float* cp = wsc;
        int gcnt = 0;
        #pragma unroll
        for (int tt = 0; tt < 8; ++tt) {
            const int j0 = 4 * lane + 128 * tt;
            float4 zv = *(const float4*)(zr + j0);
            float4 pv;
            pv.x = ((vmask >> (4 * tt + 0)) & 1u) ? fmaxf(zv.x - tau, 0.0f) : 0.f;
            pv.y = ((vmask >> (4 * tt + 1)) & 1u) ? fmaxf(zv.y - tau, 0.0f) : 0.f;
            pv.z = ((vmask >> (4 * tt + 2)) & 1u) ? fmaxf(zv.z - tau, 0.0f) : 0.f;
            pv.w = ((vmask >> (4 * tt + 3)) & 1u) ? fmaxf(zv.w - tau, 0.0f) : 0.f;
            if (write_attn) *(float4*)(arow + j0) = pv;

            #pragma unroll
            for (int e = 0; e < 4; ++e) {
                float pe = (&pv.x)[e];
                bool a = pe > 0.0f;
                unsigned bb = __ballot_sync(0xFFFFFFFFu, a);
                int base = gcnt;
                if (a) {
                    int ps = base + __popc(bb & lt);
                    if (ps < CAPP) {
                        cp[2 * ps]     = pe;
                        cp[2 * ps + 1] = __int_as_float(j0 + e);
                    } else {
                        const float2 vv = vb2[(j0 + e) * 32 + lane];
                        acc2.x += pe * vv.x;
                        acc2.y += pe * vv.y;
                    }
                }
                gcnt += __popc(bb);
            }
        }
        __syncwarp();
        const int cn = gcnt < CAPP ? gcnt : CAPP;
        int i = 0;
        for (; i + 4 <= cn; i += 4) {
            float4 e0 = *(const float4*)(cp + 2 * i);
            float4 e1 = *(const float4*)(cp + 2 * i + 4);
            const float2 v0 = vb2[__float_as_int(e0.y) * 32 + lane];
            const float2 v1 = vb2[__float_as_int(e0.w) * 32 + lane];
            const float2 v2 = vb2[__float_as_int(e1.y) * 32 + lane];
            const float2 v3 = vb2[__float_as_int(e1.w) * 32 + lane];
            acc2.x += e0.x * v0.x;  acc2.y += e0.x * v0.y;
            acc2.x += e0.z * v1.x;  acc2.y += e0.z * v1.y;
            acc2.x += e1.x * v2.x;  acc2.y += e1.x * v2.y;
            acc2.x += e1.z * v3.x;  acc2.y += e1.z * v3.y;
        }
        for (; i < cn; ++i) {
            float p = cp[2 * i];
            int  j  = __float_as_int(cp[2 * i + 1]);
            const float2 vv = vb2[j * 32 + lane];
            acc2.x += p * vv.x;
            acc2.y += p * vv.y;
        }
    }

    *(float2*)(out + ((size_t)(b * LQ + q0 + w)) * DH + 2 * lane) = acc2;
}

// --------------------------------------------------------------------------
extern "C" void kernel_launch(void* const* d_in, const int* in_sizes, int n_in,
                              void* d_out, int out_size) {
    const float* q = (const float*)d_in[0];
    const float* k = (const float*)d_in[1];
    const float* v = (const float*)d_in[2];
    const void*  m = d_in[3];

    float* out = (float*)d_out;
    long long out_elems  = (long long)B_ * LQ * DH;
    long long attn_elems = (long long)B_ * LQ * LK;
    int write_attn = ((long long)out_size >= out_elems + attn_elems) ? 1 : 0;
    float* attn = out + (size_t)out_elems;

    prep_kernel<<<KELEMS / 4 / 256, 256>>>(k, (const unsigned char*)m);

    cudaFuncSetAttribute(sparse_attn_kernel,
                         cudaFuncAttributeMaxDynamicSharedMemorySize, SMEM_BYTES);

    dim3 grid(LQ / QT, B_);
    sparse_attn_kernel<<<grid, NTHR, SMEM_BYTES>>>(q, v, m, out, attn, write_attn);
}